// round 4
// baseline (speedup 1.0000x reference)
#include <cuda_runtime.h>
#include <cuda_bf16.h>
#include <cstdint>

// ---------------- problem constants (fixed shapes) ----------------
#define N_NODES 200000
#define N_EDGES 1000000
#define D_NODE  128
#define D_EDGE  64
#define HDIM    256
#define NGRAPH  512

#define NODE_TILES ((N_NODES + 127) / 128)   // 1563
#define EDGE_TILES ((N_EDGES + 127) / 128)   // 7813

// ---------------- scratch (device globals; no allocation) ----------------
__device__ float d_S_node[NGRAPH * HDIM];
__device__ float d_S_edge[NGRAPH * HDIM];
__device__ int   d_cnt_node[NGRAPH];
__device__ int   d_cnt_edge[NGRAPH];
__device__ unsigned short d_eb[N_EDGES];     // graph id per edge
__device__ int   d_esorted[N_EDGES];         // edge ids sorted by graph
__device__ int   d_cursor[NGRAPH];
__device__ __nv_bfloat16 d_Wt_node[HDIM * D_NODE];  // [n][k]  (transposed, bf16)
__device__ __nv_bfloat16 d_Wt_edge[HDIM * D_EDGE];  // [n][k]

// ---------------- smem layout for the GEMM kernel ----------------
// Ws: 256 x (128+8) bf16 = 69632 B   (edge phase uses 256 x 72 within it)
// As: 128 x (128+8) bf16 = 34816 B
#define WS_OFF   0
#define AS_OFF   69632
#define GID_OFF  (AS_OFF + 34816)        // 128 ints
#define ES_OFF   (GID_OFF + 512)         // 128 ints
#define ACC_OFF  (ES_OFF + 512)          // 256 floats
#define BIAS_OFF (ACC_OFF + 1024)        // 256 floats
#define SG_OFF   (BIAS_OFF + 1024)       // 2 ints
#define SMEM_BYTES (SG_OFF + 16)

// ---------------- small kernels ----------------
__global__ void k_zero() {
    int i = blockIdx.x * blockDim.x + threadIdx.x;
    int stride = gridDim.x * blockDim.x;
    for (int j = i; j < NGRAPH * HDIM; j += stride) { d_S_node[j] = 0.f; d_S_edge[j] = 0.f; }
    for (int j = i; j < NGRAPH; j += stride) { d_cnt_node[j] = 0; d_cnt_edge[j] = 0; }
}

__global__ void k_prep(const float* __restrict__ Wn1, const float* __restrict__ We1) {
    int i = blockIdx.x * blockDim.x + threadIdx.x;
    int stride = gridDim.x * blockDim.x;
    for (int j = i; j < HDIM * D_NODE; j += stride) {
        int n = j / D_NODE, k = j % D_NODE;
        d_Wt_node[j] = __float2bfloat16(Wn1[k * HDIM + n]);
    }
    for (int j = i; j < HDIM * D_EDGE; j += stride) {
        int n = j / D_EDGE, k = j % D_EDGE;
        d_Wt_edge[j] = __float2bfloat16(We1[k * HDIM + n]);
    }
}

__global__ void k_nodehist(const int* __restrict__ batch_idx) {
    __shared__ int h[NGRAPH];
    for (int j = threadIdx.x; j < NGRAPH; j += blockDim.x) h[j] = 0;
    __syncthreads();
    int i = blockIdx.x * blockDim.x + threadIdx.x;
    int stride = gridDim.x * blockDim.x;
    for (int n = i; n < N_NODES; n += stride) atomicAdd(&h[batch_idx[n]], 1);
    __syncthreads();
    for (int j = threadIdx.x; j < NGRAPH; j += blockDim.x)
        if (h[j]) atomicAdd(&d_cnt_node[j], h[j]);
}

__global__ void k_edgeprep(const int* __restrict__ edge_src, const int* __restrict__ batch_idx) {
    __shared__ int h[NGRAPH];
    for (int j = threadIdx.x; j < NGRAPH; j += blockDim.x) h[j] = 0;
    __syncthreads();
    int i = blockIdx.x * blockDim.x + threadIdx.x;
    int stride = gridDim.x * blockDim.x;
    for (int e = i; e < N_EDGES; e += stride) {
        int g = batch_idx[edge_src[e]];
        d_eb[e] = (unsigned short)g;
        atomicAdd(&h[g], 1);
    }
    __syncthreads();
    for (int j = threadIdx.x; j < NGRAPH; j += blockDim.x)
        if (h[j]) atomicAdd(&d_cnt_edge[j], h[j]);
}

__global__ void k_scan() {
    // exclusive prefix sum of d_cnt_edge -> d_cursor (512 elems, 512 threads)
    __shared__ int wsum[16];
    int tid = threadIdx.x;
    int lane = tid & 31, w = tid >> 5;
    int v = d_cnt_edge[tid];
    int s = v;
    #pragma unroll
    for (int o = 1; o < 32; o <<= 1) {
        int t = __shfl_up_sync(0xffffffffu, s, o);
        if (lane >= o) s += t;
    }
    if (lane == 31) wsum[w] = s;
    __syncthreads();
    if (tid == 0) {
        int run = 0;
        for (int i = 0; i < 16; i++) { int t = wsum[i]; wsum[i] = run; run += t; }
    }
    __syncthreads();
    int incl = s + wsum[w];
    d_cursor[tid] = incl - v;   // exclusive
}

__global__ void k_scatter() {
    int i = blockIdx.x * blockDim.x + threadIdx.x;
    int stride = gridDim.x * blockDim.x;
    for (int e = i; e < N_EDGES; e += stride) {
        int g = (int)d_eb[e];
        int p = atomicAdd(&d_cursor[g], 1);
        d_esorted[p] = e;
    }
}

// ---------------- first-layer GEMM + segmented column sums ----------------
// 512 threads = 16 warps: warpM = warp&3 (32-row slices), warpN = warp>>2 (64-col slices)
// warp tile 32x64, mma m16n8k16 bf16, fp32 accum.
template<int K, int KPAD, int KSTEPS>
__device__ __forceinline__ void gemm_phase(
    const float* __restrict__ A_gmem, const float* __restrict__ bias_g,
    const __nv_bfloat16* __restrict__ Wt_g,
    const int* __restrict__ batch_idx, int n_rows_total, int n_tiles,
    bool is_edge, float* __restrict__ S_out, char* smem)
{
    __nv_bfloat16* Ws = (__nv_bfloat16*)(smem + WS_OFF);
    __nv_bfloat16* As = (__nv_bfloat16*)(smem + AS_OFF);
    int*   gid_s  = (int*)(smem + GID_OFF);
    int*   es_s   = (int*)(smem + ES_OFF);
    float* accs   = (float*)(smem + ACC_OFF);
    float* bias_s = (float*)(smem + BIAS_OFF);
    int*   sg     = (int*)(smem + SG_OFF);

    const int tid = threadIdx.x;

    // load transposed weights [n][k] -> smem padded rows
    const uint32_t* Wg32 = (const uint32_t*)Wt_g;
    for (int j = tid; j < HDIM * K / 2; j += 512) {
        int n = j / (K / 2), k2 = j % (K / 2);
        *(uint32_t*)&Ws[n * KPAD + 2 * k2] = Wg32[j];
    }
    if (tid < HDIM) bias_s[tid] = bias_g[tid];
    __syncthreads();

    const int lane = tid & 31, warp = tid >> 5;
    const int wm = (warp & 3) * 32;
    const int wn = (warp >> 2) * 64;
    const int gID = lane >> 2, tig = lane & 3;

    for (int t = blockIdx.x; t < n_tiles; t += gridDim.x) {
        int r0 = t * 128;
        int rows = n_rows_total - r0; if (rows > 128) rows = 128;

        if (tid < 128) {
            int gi = -1, e = -1;
            if (tid < rows) {
                if (is_edge) { e = d_esorted[r0 + tid]; gi = (int)d_eb[e]; }
                else         { e = r0 + tid;            gi = batch_idx[e]; }
            }
            es_s[tid]  = e;
            gid_s[tid] = gi;
        }
        __syncthreads();
        if (tid == 0) { sg[0] = gid_s[0]; sg[1] = gid_s[rows - 1]; }

        // load A tile (rows x K fp32) -> bf16 smem, zero-pad missing rows
        const int QK = K / 4;  // float4 per row
        for (int j = tid; j < 128 * QK; j += 512) {
            int r = j / QK, q = j % QK;
            float4 v = make_float4(0.f, 0.f, 0.f, 0.f);
            int e = es_s[r];
            if (e >= 0) v = *(const float4*)(A_gmem + (size_t)e * K + q * 4);
            __nv_bfloat162 p0 = __float22bfloat162_rn(make_float2(v.x, v.y));
            __nv_bfloat162 p1 = __float22bfloat162_rn(make_float2(v.z, v.w));
            *(__nv_bfloat162*)&As[r * KPAD + q * 4]     = p0;
            *(__nv_bfloat162*)&As[r * KPAD + q * 4 + 2] = p1;
        }
        __syncthreads();

        // ---- mainloop ----
        float c[2][8][4];
        #pragma unroll
        for (int mf = 0; mf < 2; mf++)
            #pragma unroll
            for (int nf = 0; nf < 8; nf++)
                #pragma unroll
                for (int r = 0; r < 4; r++) c[mf][nf][r] = 0.f;

        #pragma unroll
        for (int ks = 0; ks < KSTEPS; ks++) {
            const int kk = ks * 16;
            uint32_t a[2][4];
            #pragma unroll
            for (int mf = 0; mf < 2; mf++) {
                const __nv_bfloat16* ap = &As[(wm + mf * 16 + gID) * KPAD + kk + 2 * tig];
                a[mf][0] = *(const uint32_t*)ap;
                a[mf][1] = *(const uint32_t*)(ap + 8 * KPAD);
                a[mf][2] = *(const uint32_t*)(ap + 8);
                a[mf][3] = *(const uint32_t*)(ap + 8 * KPAD + 8);
            }
            #pragma unroll
            for (int nf = 0; nf < 8; nf++) {
                const __nv_bfloat16* bp = &Ws[(wn + nf * 8 + gID) * KPAD + kk + 2 * tig];
                uint32_t b0 = *(const uint32_t*)bp;
                uint32_t b1 = *(const uint32_t*)(bp + 8);
                #pragma unroll
                for (int mf = 0; mf < 2; mf++) {
                    asm volatile(
                        "mma.sync.aligned.m16n8k16.row.col.f32.bf16.bf16.f32 "
                        "{%0,%1,%2,%3}, {%4,%5,%6,%7}, {%8,%9}, {%0,%1,%2,%3};\n"
                        : "+f"(c[mf][nf][0]), "+f"(c[mf][nf][1]),
                          "+f"(c[mf][nf][2]), "+f"(c[mf][nf][3])
                        : "r"(a[mf][0]), "r"(a[mf][1]), "r"(a[mf][2]), "r"(a[mf][3]),
                          "r"(b0), "r"(b1));
                }
            }
        }

        // bias + relu
        #pragma unroll
        for (int nf = 0; nf < 8; nf++) {
            float b0 = bias_s[wn + nf * 8 + 2 * tig];
            float b1 = bias_s[wn + nf * 8 + 2 * tig + 1];
            #pragma unroll
            for (int mf = 0; mf < 2; mf++) {
                c[mf][nf][0] = fmaxf(c[mf][nf][0] + b0, 0.f);
                c[mf][nf][1] = fmaxf(c[mf][nf][1] + b1, 0.f);
                c[mf][nf][2] = fmaxf(c[mf][nf][2] + b0, 0.f);
                c[mf][nf][3] = fmaxf(c[mf][nf][3] + b1, 0.f);
            }
        }

        // segmented column sums (rows sorted by graph within tile)
        int g_lo = sg[0], g_hi = sg[1];
        for (int g = g_lo; g <= g_hi; ++g) {
            if (tid < 256) accs[tid] = 0.f;
            __syncthreads();
            bool m[2][2];
            #pragma unroll
            for (int mf = 0; mf < 2; mf++) {
                m[mf][0] = (gid_s[wm + mf * 16 + gID]     == g);
                m[mf][1] = (gid_s[wm + mf * 16 + gID + 8] == g);
            }
            #pragma unroll
            for (int nf = 0; nf < 8; nf++) {
                float s0 = 0.f, s1 = 0.f;
                #pragma unroll
                for (int mf = 0; mf < 2; mf++) {
                    if (m[mf][0]) { s0 += c[mf][nf][0]; s1 += c[mf][nf][1]; }
                    if (m[mf][1]) { s0 += c[mf][nf][2]; s1 += c[mf][nf][3]; }
                }
                #pragma unroll
                for (int off = 4; off < 32; off <<= 1) {
                    s0 += __shfl_xor_sync(0xffffffffu, s0, off);
                    s1 += __shfl_xor_sync(0xffffffffu, s1, off);
                }
                if (gID == 0) {
                    atomicAdd(&accs[wn + nf * 8 + 2 * tig],     s0);
                    atomicAdd(&accs[wn + nf * 8 + 2 * tig + 1], s1);
                }
            }
            __syncthreads();
            if (tid < 256) {
                float v = accs[tid];
                if (v != 0.f) atomicAdd(&S_out[g * HDIM + tid], v);
            }
            __syncthreads();
        }
    }
    __syncthreads();
}

__global__ void __launch_bounds__(512)
k_gemm(const float* __restrict__ x, const float* __restrict__ edge_attr,
       const int* __restrict__ batch_idx,
       const float* __restrict__ bn1, const float* __restrict__ be1)
{
    extern __shared__ char smem[];
    gemm_phase<D_NODE, D_NODE + 8, D_NODE / 16>(
        x, bn1, d_Wt_node, batch_idx, N_NODES, NODE_TILES, false, d_S_node, smem);
    gemm_phase<D_EDGE, D_EDGE + 8, D_EDGE / 16>(
        edge_attr, be1, d_Wt_edge, nullptr, N_EDGES, EDGE_TILES, true, d_S_edge, smem);
}

// ---------------- tail: means -> layer-2 -> combine ----------------
__global__ void __launch_bounds__(256)
k_finalize(const float* __restrict__ Wn2, const float* __restrict__ bn2,
           const float* __restrict__ We2, const float* __restrict__ be2,
           const float* __restrict__ Wc,  const float* __restrict__ bc,
           float* __restrict__ out)
{
    __shared__ float mn[8][HDIM], me[8][HDIM], gr[8][HDIM];
    __shared__ int fn[8], fe[8];
    const int tid = threadIdx.x;
    const int gbase = blockIdx.x * 8;

    #pragma unroll
    for (int gg = 0; gg < 8; gg++) {
        int g = gbase + gg;
        int cn = d_cnt_node[g], ce = d_cnt_edge[g];
        if (tid == 0) { fn[gg] = cn; fe[gg] = ce; }
        mn[gg][tid] = (cn > 0) ? d_S_node[g * HDIM + tid] / (float)cn : 0.f;
        me[gg][tid] = (ce > 0) ? d_S_edge[g * HDIM + tid] / (float)ce : 0.f;
    }
    __syncthreads();

    float an[8], ae[8];
    #pragma unroll
    for (int gg = 0; gg < 8; gg++) { an[gg] = 0.f; ae[gg] = 0.f; }
    for (int j = 0; j < HDIM; j++) {
        float w1 = Wn2[j * HDIM + tid];
        float w2 = We2[j * HDIM + tid];
        #pragma unroll
        for (int gg = 0; gg < 8; gg++) {
            an[gg] += mn[gg][j] * w1;
            ae[gg] += me[gg][j] * w2;
        }
    }
    float b2n = bn2[tid], b2e = be2[tid];
    #pragma unroll
    for (int gg = 0; gg < 8; gg++) {
        float nr = (fn[gg] > 0) ? an[gg] + b2n : 0.f;
        float er = (fe[gg] > 0) ? ae[gg] + b2e : 0.f;
        gr[gg][tid] = nr + er;
    }
    __syncthreads();

    float ao[8];
    #pragma unroll
    for (int gg = 0; gg < 8; gg++) ao[gg] = 0.f;
    for (int j = 0; j < HDIM; j++) {
        float w = Wc[j * HDIM + tid];
        #pragma unroll
        for (int gg = 0; gg < 8; gg++) ao[gg] += gr[gg][j] * w;
    }
    float bcv = bc[tid];
    #pragma unroll
    for (int gg = 0; gg < 8; gg++)
        out[(gbase + gg) * HDIM + tid] = ao[gg] + bcv;
}

// ---------------- launch ----------------
extern "C" void kernel_launch(void* const* d_in, const int* in_sizes, int n_in,
                              void* d_out, int out_size)
{
    const float* x         = (const float*)d_in[0];
    const float* edge_attr = (const float*)d_in[1];
    const int*   batch_idx = (const int*)d_in[2];
    const int*   edge_src  = (const int*)d_in[3];
    const float* Wn1 = (const float*)d_in[4];
    const float* bn1 = (const float*)d_in[5];
    const float* Wn2 = (const float*)d_in[6];
    const float* bn2 = (const float*)d_in[7];
    const float* We1 = (const float*)d_in[8];
    const float* be1 = (const float*)d_in[9];
    const float* We2 = (const float*)d_in[10];
    const float* be2 = (const float*)d_in[11];
    const float* Wc  = (const float*)d_in[12];
    const float* bc  = (const float*)d_in[13];
    float* out = (float*)d_out;

    (void)in_sizes; (void)n_in; (void)out_size;

    cudaFuncSetAttribute(k_gemm, cudaFuncAttributeMaxDynamicSharedMemorySize, SMEM_BYTES);

    k_zero<<<256, 256>>>();
    k_prep<<<64, 256>>>(Wn1, We1);
    k_nodehist<<<200, 256>>>(batch_idx);
    k_edgeprep<<<512, 256>>>(edge_src, batch_idx);
    k_scan<<<1, 512>>>();
    k_scatter<<<512, 256>>>();
    k_gemm<<<148, 512, SMEM_BYTES>>>(x, edge_attr, batch_idx, bn1, be1);
    k_finalize<<<64, 256>>>(Wn2, bn2, We2, be2, Wc, bc, out);
}

// round 6
// speedup vs baseline: 1.0910x; 1.0910x over previous
#include <cuda_runtime.h>
#include <cuda_bf16.h>
#include <cstdint>

// ---------------- problem constants (fixed shapes) ----------------
#define N_NODES 200000
#define N_EDGES 1000000
#define D_NODE  128
#define D_EDGE  64
#define HDIM    256
#define NGRAPH  512

#define NODE_TILES ((N_NODES + 127) / 128)   // 1563
#define EDGE_TILES ((N_EDGES + 127) / 128)   // 7813

// ---------------- scratch (device globals; no allocation) ----------------
__device__ float d_S_node[NGRAPH * HDIM];
__device__ float d_S_edge[NGRAPH * HDIM];
__device__ int   d_cnt_node[NGRAPH];
__device__ int   d_cnt_edge[NGRAPH];
__device__ unsigned short d_eb[N_EDGES];     // graph id per edge
__device__ int   d_esorted[N_EDGES];         // edge ids sorted by graph
__device__ int   d_cursor[NGRAPH];
__device__ __nv_bfloat16 d_Wt_node[HDIM * D_NODE];  // [n][k]  (transposed, bf16)
__device__ __nv_bfloat16 d_Wt_edge[HDIM * D_EDGE];  // [n][k]

// ---------------- smem layout for the GEMM kernels ----------------
// Ws : 256 x (128+8) bf16 = 69632 B  (edge phase uses 256 x 72 inside it)
// As : 128 x (128+8) bf16 = 34816 B
// Cs : 64 x 264 fp32      = 67584 B  (C staging, half tile per pass)
#define CPAD 264
#define WS_OFF   0
#define AS_OFF   69632
#define CS_OFF   (AS_OFF + 34816)          // 104448
#define GID_OFF  (CS_OFF + 67584)          // 172032 : 128 ints
#define ES_OFF   (GID_OFF + 512)           // 128 ints
#define BIAS_OFF (ES_OFF + 512)            // 256 floats
#define SMEM_BYTES (BIAS_OFF + 1024)       // 174080

// ---------------- asm helpers ----------------
#define LDSM_X4(r0, r1, r2, r3, addr)                                          \
    asm volatile("ldmatrix.sync.aligned.m8n8.x4.shared.b16 {%0,%1,%2,%3}, [%4];" \
                 : "=r"(r0), "=r"(r1), "=r"(r2), "=r"(r3) : "r"(addr))

#define MMA16816(c0, c1, c2, c3, a0, a1, a2, a3, b0, b1)                       \
    asm volatile(                                                              \
        "mma.sync.aligned.m16n8k16.row.col.f32.bf16.bf16.f32 "                 \
        "{%0,%1,%2,%3}, {%4,%5,%6,%7}, {%8,%9}, {%0,%1,%2,%3};\n"              \
        : "+f"(c0), "+f"(c1), "+f"(c2), "+f"(c3)                               \
        : "r"(a0), "r"(a1), "r"(a2), "r"(a3), "r"(b0), "r"(b1))

// ---------------- launch #1: zero the count buffers (MUST precede k_setup:
// histogram blocks in k_setup atomicAdd into these concurrently with other
// blocks, so zeroing inside k_setup is a race — that was the R4 bug) -------
__global__ void k_zero0() {
    int tid = threadIdx.x;
    if (tid < NGRAPH) { d_cnt_node[tid] = 0; d_cnt_edge[tid] = 0; }
}

// ---------------- launch #2: zero sums + weight transpose + histograms ----
__global__ void k_setup(const float* __restrict__ Wn1, const float* __restrict__ We1,
                        const int* __restrict__ batch_idx, const int* __restrict__ edge_src)
{
    const int b = blockIdx.x;
    const int tid = threadIdx.x;
    if (b < 64) {
        // weight transpose + bf16 convert
        int i = b * 256 + tid;
        for (int j = i; j < HDIM * D_NODE; j += 64 * 256) {
            int n = j / D_NODE, k = j % D_NODE;
            d_Wt_node[j] = __float2bfloat16(Wn1[k * HDIM + n]);
        }
        for (int j = i; j < HDIM * D_EDGE; j += 64 * 256) {
            int n = j / D_EDGE, k = j % D_EDGE;
            d_Wt_edge[j] = __float2bfloat16(We1[k * HDIM + n]);
        }
    } else if (b < 128) {
        // zero the sum buffers (only read by later kernels — no race)
        int i = (b - 64) * 256 + tid;
        for (int j = i; j < NGRAPH * HDIM; j += 64 * 256) { d_S_node[j] = 0.f; d_S_edge[j] = 0.f; }
    } else if (b < 328) {
        // node histogram
        __shared__ int h[NGRAPH];
        for (int j = tid; j < NGRAPH; j += 256) h[j] = 0;
        __syncthreads();
        int i = (b - 128) * 256 + tid;
        for (int n = i; n < N_NODES; n += 200 * 256) atomicAdd(&h[batch_idx[n]], 1);
        __syncthreads();
        for (int j = tid; j < NGRAPH; j += 256)
            if (h[j]) atomicAdd(&d_cnt_node[j], h[j]);
    } else {
        // edge graph-id + histogram
        __shared__ int h[NGRAPH];
        for (int j = tid; j < NGRAPH; j += 256) h[j] = 0;
        __syncthreads();
        int i = (b - 328) * 256 + tid;
        for (int e = i; e < N_EDGES; e += 512 * 256) {
            int g = batch_idx[edge_src[e]];
            d_eb[e] = (unsigned short)g;
            atomicAdd(&h[g], 1);
        }
        __syncthreads();
        for (int j = tid; j < NGRAPH; j += 256)
            if (h[j]) atomicAdd(&d_cnt_edge[j], h[j]);
    }
}

// ---------------- launch #3: exclusive prefix sum of edge counts ----------
__global__ void k_scan() {
    __shared__ int wsum[16];
    int tid = threadIdx.x;
    int lane = tid & 31, w = tid >> 5;
    int v = d_cnt_edge[tid];
    int s = v;
    #pragma unroll
    for (int o = 1; o < 32; o <<= 1) {
        int t = __shfl_up_sync(0xffffffffu, s, o);
        if (lane >= o) s += t;
    }
    if (lane == 31) wsum[w] = s;
    __syncthreads();
    if (tid == 0) {
        int run = 0;
        for (int i = 0; i < 16; i++) { int t = wsum[i]; wsum[i] = run; run += t; }
    }
    __syncthreads();
    d_cursor[tid] = s + wsum[w] - v;   // exclusive
}

// ---------------- launch #5: counting-sort scatter of edge ids ------------
__global__ void k_scatter() {
    int i = blockIdx.x * blockDim.x + threadIdx.x;
    int stride = gridDim.x * blockDim.x;
    for (int e = i; e < N_EDGES; e += stride) {
        int g = (int)d_eb[e];
        int p = atomicAdd(&d_cursor[g], 1);
        d_esorted[p] = e;
    }
}

// ---------------- first-layer GEMM + segmented column sums ----------------
// 512 threads = 16 warps: warpM = warp&3 (32-row slices), warpN = warp>>2 (64-col slices)
// warp tile 32x64, mma m16n8k16 bf16, fp32 accum, LDSM fragment loads.
template<int K, int KPAD, int KSTEPS, int NITER>
__device__ __forceinline__ void gemm_phase(
    const float* __restrict__ A_gmem, const float* __restrict__ bias_g,
    const __nv_bfloat16* __restrict__ Wt_g,
    const int* __restrict__ batch_idx, int n_rows_total, int n_tiles,
    bool is_edge, float* __restrict__ S_out, char* smem, uint32_t sbase)
{
    __nv_bfloat16* Ws = (__nv_bfloat16*)(smem + WS_OFF);
    __nv_bfloat16* As = (__nv_bfloat16*)(smem + AS_OFF);
    float* Cs     = (float*)(smem + CS_OFF);
    int*   gid_s  = (int*)(smem + GID_OFF);
    int*   es_s   = (int*)(smem + ES_OFF);
    float* bias_s = (float*)(smem + BIAS_OFF);

    const int tid = threadIdx.x;

    // load transposed weights [n][k] -> smem padded rows
    const uint32_t* Wg32 = (const uint32_t*)Wt_g;
    for (int j = tid; j < HDIM * K / 2; j += 512) {
        int n = j / (K / 2), k2 = j % (K / 2);
        *(uint32_t*)&Ws[n * KPAD + 2 * k2] = Wg32[j];
    }
    if (tid < HDIM) bias_s[tid] = bias_g[tid];
    __syncthreads();

    const int lane = tid & 31, warp = tid >> 5;
    const int wm = (warp & 3) * 32;
    const int wn = (warp >> 2) * 64;
    const int gID = lane >> 2, tig = lane & 3;
    const int myhalf = wm >> 6;         // 0 for wm {0,32}, 1 for {64,96}

    // ldmatrix lane addresses (byte offsets in smem window)
    const uint32_t a_addr0 = sbase + AS_OFF +
        (uint32_t)(((wm + (lane & 15)) * KPAD + ((lane >> 4) << 3)) * 2);
    const uint32_t a_addr1 = a_addr0 + (uint32_t)(16 * KPAD * 2);
    const int brow = (lane & 7) + ((lane >> 4) << 3);
    const int bkof = ((lane >> 3) & 1) << 3;
    const uint32_t b_addr0 = sbase + WS_OFF +
        (uint32_t)(((wn + brow) * KPAD + bkof) * 2);

    const int QK = K / 4;   // float4 per row

    for (int t = blockIdx.x; t < n_tiles; t += gridDim.x) {
        int r0 = t * 128;
        int rows = n_rows_total - r0; if (rows > 128) rows = 128;

        if (tid < 128) {
            int gi = -1, e = -1;
            if (tid < rows) {
                if (is_edge) { e = d_esorted[r0 + tid]; gi = (int)d_eb[e]; }
                else         { e = r0 + tid;            gi = batch_idx[e]; }
            }
            es_s[tid]  = e;
            gid_s[tid] = gi;
        }
        __syncthreads();

        // ---- gather A tile in chunks of 4 float4 (MLP=4, bounded reg use) ----
        #pragma unroll
        for (int base = 0; base < NITER; base += 4) {
            float4 v[4];
            #pragma unroll
            for (int i = 0; i < 4; i++) {
                int j = tid + (base + i) * 512;
                int r = j / QK, q = j % QK;
                int e = es_s[r];
                v[i] = (e >= 0) ? *(const float4*)(A_gmem + (size_t)e * K + q * 4)
                                : make_float4(0.f, 0.f, 0.f, 0.f);
            }
            #pragma unroll
            for (int i = 0; i < 4; i++) {
                int j = tid + (base + i) * 512;
                int r = j / QK, q = j % QK;
                __nv_bfloat162 p0 = __float22bfloat162_rn(make_float2(v[i].x, v[i].y));
                __nv_bfloat162 p1 = __float22bfloat162_rn(make_float2(v[i].z, v[i].w));
                *(__nv_bfloat162*)&As[r * KPAD + q * 4]     = p0;
                *(__nv_bfloat162*)&As[r * KPAD + q * 4 + 2] = p1;
            }
        }
        __syncthreads();

        // ---- mainloop (ldmatrix + mma) ----
        float c[2][8][4];
        #pragma unroll
        for (int mf = 0; mf < 2; mf++)
            #pragma unroll
            for (int nf = 0; nf < 8; nf++)
                #pragma unroll
                for (int r = 0; r < 4; r++) c[mf][nf][r] = 0.f;

        #pragma unroll
        for (int ks = 0; ks < KSTEPS; ks++) {
            const uint32_t koff = (uint32_t)(ks * 16 * 2);
            uint32_t a[2][4];
            LDSM_X4(a[0][0], a[0][1], a[0][2], a[0][3], a_addr0 + koff);
            LDSM_X4(a[1][0], a[1][1], a[1][2], a[1][3], a_addr1 + koff);
            #pragma unroll
            for (int nfp = 0; nfp < 4; nfp++) {
                uint32_t b0, b1, b2, b3;
                LDSM_X4(b0, b1, b2, b3,
                        b_addr0 + (uint32_t)(nfp * 16 * KPAD * 2) + koff);
                const int nf = 2 * nfp;
                MMA16816(c[0][nf][0], c[0][nf][1], c[0][nf][2], c[0][nf][3],
                         a[0][0], a[0][1], a[0][2], a[0][3], b0, b1);
                MMA16816(c[1][nf][0], c[1][nf][1], c[1][nf][2], c[1][nf][3],
                         a[1][0], a[1][1], a[1][2], a[1][3], b0, b1);
                MMA16816(c[0][nf+1][0], c[0][nf+1][1], c[0][nf+1][2], c[0][nf+1][3],
                         a[0][0], a[0][1], a[0][2], a[0][3], b2, b3);
                MMA16816(c[1][nf+1][0], c[1][nf+1][1], c[1][nf+1][2], c[1][nf+1][3],
                         a[1][0], a[1][1], a[1][2], a[1][3], b2, b3);
            }
        }

        // ---- bias + relu ----
        #pragma unroll
        for (int nf = 0; nf < 8; nf++) {
            float b0 = bias_s[wn + nf * 8 + 2 * tig];
            float b1 = bias_s[wn + nf * 8 + 2 * tig + 1];
            #pragma unroll
            for (int mf = 0; mf < 2; mf++) {
                c[mf][nf][0] = fmaxf(c[mf][nf][0] + b0, 0.f);
                c[mf][nf][1] = fmaxf(c[mf][nf][1] + b1, 0.f);
                c[mf][nf][2] = fmaxf(c[mf][nf][2] + b0, 0.f);
                c[mf][nf][3] = fmaxf(c[mf][nf][3] + b1, 0.f);
            }
        }

        // ---- segmented column sums via fp32 smem staging, 2 passes of 64 rows ----
        const int col = tid & 255;
        const int rh  = tid >> 8;
        #pragma unroll
        for (int p = 0; p < 2; p++) {
            __syncthreads();
            if (myhalf == p) {
                #pragma unroll
                for (int mf = 0; mf < 2; mf++) {
                    int rl = (wm & 63) + mf * 16 + gID;
                    #pragma unroll
                    for (int nf = 0; nf < 8; nf++) {
                        int cl = wn + nf * 8 + 2 * tig;
                        *(float2*)&Cs[rl * CPAD + cl] =
                            make_float2(c[mf][nf][0], c[mf][nf][1]);
                        *(float2*)&Cs[(rl + 8) * CPAD + cl] =
                            make_float2(c[mf][nf][2], c[mf][nf][3]);
                    }
                }
            }
            __syncthreads();
            // column-serial segmented reduction over 32 rows per thread
            int grow = p * 64 + rh * 32;
            float acc = 0.f;
            int cur = gid_s[grow];
            #pragma unroll 8
            for (int r = 0; r < 32; r++) {
                int g  = gid_s[grow + r];
                float cv = Cs[(rh * 32 + r) * CPAD + col];
                if (g != cur) {
                    if (cur >= 0) atomicAdd(&S_out[cur * HDIM + col], acc);
                    acc = 0.f; cur = g;
                }
                acc += cv;
            }
            if (cur >= 0) atomicAdd(&S_out[cur * HDIM + col], acc);
        }
        __syncthreads();
    }
}

// ---------------- launch #4: node GEMM (profiled slot) --------------------
__global__ void __launch_bounds__(512)
k_gemm_node(const float* __restrict__ x, const int* __restrict__ batch_idx,
            const float* __restrict__ bn1)
{
    extern __shared__ char smem[];
    uint32_t sbase = (uint32_t)__cvta_generic_to_shared(smem);
    gemm_phase<D_NODE, D_NODE + 8, D_NODE / 16, 128 * (D_NODE / 4) / 512>(
        x, bn1, d_Wt_node, batch_idx, N_NODES, NODE_TILES, false, d_S_node, smem, sbase);
}

// ---------------- launch #6: edge GEMM -----------------------------------
__global__ void __launch_bounds__(512)
k_gemm_edge(const float* __restrict__ edge_attr, const float* __restrict__ be1)
{
    extern __shared__ char smem[];
    uint32_t sbase = (uint32_t)__cvta_generic_to_shared(smem);
    gemm_phase<D_EDGE, D_EDGE + 8, D_EDGE / 16, 128 * (D_EDGE / 4) / 512>(
        edge_attr, be1, d_Wt_edge, nullptr, N_EDGES, EDGE_TILES, true, d_S_edge, smem, sbase);
}

// ---------------- launch #7: means -> layer-2 -> combine ------------------
__global__ void __launch_bounds__(256)
k_finalize(const float* __restrict__ Wn2, const float* __restrict__ bn2,
           const float* __restrict__ We2, const float* __restrict__ be2,
           const float* __restrict__ Wc,  const float* __restrict__ bc,
           float* __restrict__ out)
{
    __shared__ float mn[8][HDIM], me[8][HDIM], gr[8][HDIM];
    __shared__ int fn[8], fe[8];
    const int tid = threadIdx.x;
    const int gbase = blockIdx.x * 8;

    #pragma unroll
    for (int gg = 0; gg < 8; gg++) {
        int g = gbase + gg;
        int cn = d_cnt_node[g], ce = d_cnt_edge[g];
        if (tid == 0) { fn[gg] = cn; fe[gg] = ce; }
        mn[gg][tid] = (cn > 0) ? d_S_node[g * HDIM + tid] / (float)cn : 0.f;
        me[gg][tid] = (ce > 0) ? d_S_edge[g * HDIM + tid] / (float)ce : 0.f;
    }
    __syncthreads();

    float an[8], ae[8];
    #pragma unroll
    for (int gg = 0; gg < 8; gg++) { an[gg] = 0.f; ae[gg] = 0.f; }
    for (int j = 0; j < HDIM; j++) {
        float w1 = Wn2[j * HDIM + tid];
        float w2 = We2[j * HDIM + tid];
        #pragma unroll
        for (int gg = 0; gg < 8; gg++) {
            an[gg] += mn[gg][j] * w1;
            ae[gg] += me[gg][j] * w2;
        }
    }
    float b2n = bn2[tid], b2e = be2[tid];
    #pragma unroll
    for (int gg = 0; gg < 8; gg++) {
        float nr = (fn[gg] > 0) ? an[gg] + b2n : 0.f;
        float er = (fe[gg] > 0) ? ae[gg] + b2e : 0.f;
        gr[gg][tid] = nr + er;
    }
    __syncthreads();

    float ao[8];
    #pragma unroll
    for (int gg = 0; gg < 8; gg++) ao[gg] = 0.f;
    for (int j = 0; j < HDIM; j++) {
        float w = Wc[j * HDIM + tid];
        #pragma unroll
        for (int gg = 0; gg < 8; gg++) ao[gg] += gr[gg][j] * w;
    }
    float bcv = bc[tid];
    #pragma unroll
    for (int gg = 0; gg < 8; gg++)
        out[(gbase + gg) * HDIM + tid] = ao[gg] + bcv;
}

// ---------------- launch ----------------
extern "C" void kernel_launch(void* const* d_in, const int* in_sizes, int n_in,
                              void* d_out, int out_size)
{
    const float* x         = (const float*)d_in[0];
    const float* edge_attr = (const float*)d_in[1];
    const int*   batch_idx = (const int*)d_in[2];
    const int*   edge_src  = (const int*)d_in[3];
    const float* Wn1 = (const float*)d_in[4];
    const float* bn1 = (const float*)d_in[5];
    const float* Wn2 = (const float*)d_in[6];
    const float* bn2 = (const float*)d_in[7];
    const float* We1 = (const float*)d_in[8];
    const float* be1 = (const float*)d_in[9];
    const float* We2 = (const float*)d_in[10];
    const float* be2 = (const float*)d_in[11];
    const float* Wc  = (const float*)d_in[12];
    const float* bc  = (const float*)d_in[13];
    float* out = (float*)d_out;

    (void)in_sizes; (void)n_in; (void)out_size;

    cudaFuncSetAttribute(k_gemm_node, cudaFuncAttributeMaxDynamicSharedMemorySize, SMEM_BYTES);
    cudaFuncSetAttribute(k_gemm_edge, cudaFuncAttributeMaxDynamicSharedMemorySize, SMEM_BYTES);

    k_zero0<<<1, 512>>>();                                             // #1
    k_setup<<<840, 256>>>(Wn1, We1, batch_idx, edge_src);              // #2
    k_scan<<<1, 512>>>();                                              // #3
    k_gemm_node<<<148, 512, SMEM_BYTES>>>(x, batch_idx, bn1);          // #4 (profiled)
    k_scatter<<<512, 256>>>();                                         // #5
    k_gemm_edge<<<148, 512, SMEM_BYTES>>>(edge_attr, be1);             // #6
    k_finalize<<<64, 256>>>(Wn2, bn2, We2, be2, Wc, bc, out);          // #7
}

// round 7
// speedup vs baseline: 1.4422x; 1.3220x over previous
#include <cuda_runtime.h>
#include <cuda_bf16.h>
#include <cstdint>

// ---------------- problem constants (fixed shapes) ----------------
#define N_NODES 200000
#define N_EDGES 1000000
#define D_NODE  128
#define D_EDGE  64
#define HDIM    256
#define NGRAPH  512

#define MTILE 64
#define NODE_TILES (N_NODES / MTILE)   // 3125 (exact)
#define EDGE_TILES (N_EDGES / MTILE)   // 15625 (exact)

// ---------------- scratch (device globals; no allocation) ----------------
__device__ float d_S_node[NGRAPH * HDIM];
__device__ float d_S_edge[NGRAPH * HDIM];
__device__ int   d_cnt_node[NGRAPH];
__device__ int   d_cnt_edge[NGRAPH];
__device__ unsigned short d_eb[N_EDGES];     // graph id per edge
__device__ int   d_esorted[N_EDGES];         // edge ids sorted by graph
__device__ int   d_cursor[NGRAPH];
__device__ __nv_bfloat16 d_Wt_node[HDIM * D_NODE];  // [n][k]  (transposed, bf16)
__device__ __nv_bfloat16 d_Wt_edge[HDIM * D_EDGE];  // [n][k]

// ---------------- smem layout for the GEMM kernels ----------------
// Ws : 256 x (128+8) bf16 = 69632 B  (edge phase uses 256 x 72 inside it)
// As : 64  x (128+8) bf16 = 17408 B
#define WS_OFF   0
#define AS_OFF   69632
#define GID_OFF  (AS_OFF + 17408)          // 87040 : 64 ints
#define ES_OFF   (GID_OFF + 256)           // 64 ints
#define BIAS_OFF (ES_OFF + 256)            // 256 floats
#define SMEM_BYTES (BIAS_OFF + 1024)       // 88576  -> 2 CTAs/SM (177KB < 227KB)

// ---------------- asm helpers ----------------
#define LDSM_X4(r0, r1, r2, r3, addr)                                          \
    asm volatile("ldmatrix.sync.aligned.m8n8.x4.shared.b16 {%0,%1,%2,%3}, [%4];" \
                 : "=r"(r0), "=r"(r1), "=r"(r2), "=r"(r3) : "r"(addr))

#define MMA16816(c0, c1, c2, c3, a0, a1, a2, a3, b0, b1)                       \
    asm volatile(                                                              \
        "mma.sync.aligned.m16n8k16.row.col.f32.bf16.bf16.f32 "                 \
        "{%0,%1,%2,%3}, {%4,%5,%6,%7}, {%8,%9}, {%0,%1,%2,%3};\n"              \
        : "+f"(c0), "+f"(c1), "+f"(c2), "+f"(c3)                               \
        : "r"(a0), "r"(a1), "r"(a2), "r"(a3), "r"(b0), "r"(b1))

// ---------------- launch #1: zero count buffers (must precede k_setup) ----
__global__ void k_zero0() {
    int tid = threadIdx.x;
    if (tid < NGRAPH) { d_cnt_node[tid] = 0; d_cnt_edge[tid] = 0; }
}

// ---------------- launch #2: zero sums + weight transpose + histograms ----
__global__ void k_setup(const float* __restrict__ Wn1, const float* __restrict__ We1,
                        const int* __restrict__ batch_idx, const int* __restrict__ edge_src)
{
    const int b = blockIdx.x;
    const int tid = threadIdx.x;
    if (b < 64) {
        int i = b * 256 + tid;
        for (int j = i; j < HDIM * D_NODE; j += 64 * 256) {
            int n = j / D_NODE, k = j % D_NODE;
            d_Wt_node[j] = __float2bfloat16(Wn1[k * HDIM + n]);
        }
        for (int j = i; j < HDIM * D_EDGE; j += 64 * 256) {
            int n = j / D_EDGE, k = j % D_EDGE;
            d_Wt_edge[j] = __float2bfloat16(We1[k * HDIM + n]);
        }
    } else if (b < 128) {
        int i = (b - 64) * 256 + tid;
        for (int j = i; j < NGRAPH * HDIM; j += 64 * 256) { d_S_node[j] = 0.f; d_S_edge[j] = 0.f; }
    } else if (b < 328) {
        __shared__ int h[NGRAPH];
        for (int j = tid; j < NGRAPH; j += 256) h[j] = 0;
        __syncthreads();
        int i = (b - 128) * 256 + tid;
        for (int n = i; n < N_NODES; n += 200 * 256) atomicAdd(&h[batch_idx[n]], 1);
        __syncthreads();
        for (int j = tid; j < NGRAPH; j += 256)
            if (h[j]) atomicAdd(&d_cnt_node[j], h[j]);
    } else {
        __shared__ int h[NGRAPH];
        for (int j = tid; j < NGRAPH; j += 256) h[j] = 0;
        __syncthreads();
        int i = (b - 328) * 256 + tid;
        for (int e = i; e < N_EDGES; e += 512 * 256) {
            int g = batch_idx[edge_src[e]];
            d_eb[e] = (unsigned short)g;
            atomicAdd(&h[g], 1);
        }
        __syncthreads();
        for (int j = tid; j < NGRAPH; j += 256)
            if (h[j]) atomicAdd(&d_cnt_edge[j], h[j]);
    }
}

// ---------------- launch #3: exclusive prefix sum of edge counts ----------
__global__ void k_scan() {
    __shared__ int wsum[16];
    int tid = threadIdx.x;
    int lane = tid & 31, w = tid >> 5;
    int v = d_cnt_edge[tid];
    int s = v;
    #pragma unroll
    for (int o = 1; o < 32; o <<= 1) {
        int t = __shfl_up_sync(0xffffffffu, s, o);
        if (lane >= o) s += t;
    }
    if (lane == 31) wsum[w] = s;
    __syncthreads();
    if (tid == 0) {
        int run = 0;
        for (int i = 0; i < 16; i++) { int t = wsum[i]; wsum[i] = run; run += t; }
    }
    __syncthreads();
    d_cursor[tid] = s + wsum[w] - v;   // exclusive
}

// ---------------- launch #5: counting-sort scatter of edge ids ------------
__global__ void k_scatter() {
    int i = blockIdx.x * blockDim.x + threadIdx.x;
    int stride = gridDim.x * blockDim.x;
    for (int e = i; e < N_EDGES; e += stride) {
        int g = (int)d_eb[e];
        int p = atomicAdd(&d_cursor[g], 1);
        d_esorted[p] = e;
    }
}

// ---------------- first-layer GEMM + segmented column sums ----------------
// 256 threads = 8 warps: wm = (w&1)*32 (2 M-slices), wn = (w>>1)*64 (4 N-slices)
// M-tile 64, warp tile 32x64, mma m16n8k16 bf16, fp32 accum, LDSM loads.
// Epilogue: per-graph register reduce (shfl over gID) + direct global atomics.
template<int K, int KPAD, int KSTEPS, int NITER>
__device__ __forceinline__ void gemm_phase(
    const float* __restrict__ A_gmem, const float* __restrict__ bias_g,
    const __nv_bfloat16* __restrict__ Wt_g,
    const int* __restrict__ batch_idx, int n_tiles,
    bool is_edge, float* __restrict__ S_out, char* smem, uint32_t sbase)
{
    __nv_bfloat16* Ws = (__nv_bfloat16*)(smem + WS_OFF);
    __nv_bfloat16* As = (__nv_bfloat16*)(smem + AS_OFF);
    int*   gid_s  = (int*)(smem + GID_OFF);
    int*   es_s   = (int*)(smem + ES_OFF);
    float* bias_s = (float*)(smem + BIAS_OFF);

    const int tid = threadIdx.x;

    // load transposed weights [n][k] -> smem padded rows
    const uint32_t* Wg32 = (const uint32_t*)Wt_g;
    for (int j = tid; j < HDIM * K / 2; j += 256) {
        int n = j / (K / 2), k2 = j % (K / 2);
        *(uint32_t*)&Ws[n * KPAD + 2 * k2] = Wg32[j];
    }
    if (tid < HDIM) bias_s[tid] = bias_g[tid];
    __syncthreads();

    const int lane = tid & 31, warp = tid >> 5;
    const int wm = (warp & 1) * 32;
    const int wn = (warp >> 1) * 64;
    const int gID = lane >> 2, tig = lane & 3;

    // ldmatrix lane addresses (byte offsets in smem window)
    const uint32_t a_addr0 = sbase + AS_OFF +
        (uint32_t)(((wm + (lane & 15)) * KPAD + ((lane >> 4) << 3)) * 2);
    const uint32_t a_addr1 = a_addr0 + (uint32_t)(16 * KPAD * 2);
    const int brow = (lane & 7) + ((lane >> 4) << 3);
    const int bkof = ((lane >> 3) & 1) << 3;
    const uint32_t b_addr0 = sbase + WS_OFF +
        (uint32_t)(((wn + brow) * KPAD + bkof) * 2);

    const int QK = K / 4;   // float4 per row

    for (int t = blockIdx.x; t < n_tiles; t += gridDim.x) {
        int r0 = t * MTILE;

        __syncthreads();   // protect gid_s/es_s/As from previous iteration readers
        if (tid < MTILE) {
            int e, gi;
            if (is_edge) { e = d_esorted[r0 + tid]; gi = (int)d_eb[e]; }
            else         { e = r0 + tid;            gi = batch_idx[e]; }
            es_s[tid]  = e;
            gid_s[tid] = gi;
        }
        __syncthreads();

        // ---- gather A tile in chunks of 4 float4 (MLP=4) ----
        #pragma unroll
        for (int base = 0; base < NITER; base += 4) {
            float4 v[4];
            #pragma unroll
            for (int i = 0; i < 4; i++) {
                int j = tid + (base + i) * 256;
                int r = j / QK, q = j % QK;
                v[i] = *(const float4*)(A_gmem + (size_t)es_s[r] * K + q * 4);
            }
            #pragma unroll
            for (int i = 0; i < 4; i++) {
                int j = tid + (base + i) * 256;
                int r = j / QK, q = j % QK;
                __nv_bfloat162 p0 = __float22bfloat162_rn(make_float2(v[i].x, v[i].y));
                __nv_bfloat162 p1 = __float22bfloat162_rn(make_float2(v[i].z, v[i].w));
                *(__nv_bfloat162*)&As[r * KPAD + q * 4]     = p0;
                *(__nv_bfloat162*)&As[r * KPAD + q * 4 + 2] = p1;
            }
        }
        __syncthreads();

        // row gids for this lane's fragment rows
        int gr0[2], gr1[2];
        #pragma unroll
        for (int mf = 0; mf < 2; mf++) {
            gr0[mf] = gid_s[wm + mf * 16 + gID];
            gr1[mf] = gid_s[wm + mf * 16 + gID + 8];
        }
        const int g_lo = gid_s[0];
        const int g_hi = gid_s[MTILE - 1];

        // ---- mainloop (ldmatrix + mma) ----
        float c[2][8][4];
        #pragma unroll
        for (int mf = 0; mf < 2; mf++)
            #pragma unroll
            for (int nf = 0; nf < 8; nf++)
                #pragma unroll
                for (int r = 0; r < 4; r++) c[mf][nf][r] = 0.f;

        #pragma unroll
        for (int ks = 0; ks < KSTEPS; ks++) {
            const uint32_t koff = (uint32_t)(ks * 16 * 2);
            uint32_t a[2][4];
            LDSM_X4(a[0][0], a[0][1], a[0][2], a[0][3], a_addr0 + koff);
            LDSM_X4(a[1][0], a[1][1], a[1][2], a[1][3], a_addr1 + koff);
            #pragma unroll
            for (int nfp = 0; nfp < 4; nfp++) {
                uint32_t b0, b1, b2, b3;
                LDSM_X4(b0, b1, b2, b3,
                        b_addr0 + (uint32_t)(nfp * 16 * KPAD * 2) + koff);
                const int nf = 2 * nfp;
                MMA16816(c[0][nf][0], c[0][nf][1], c[0][nf][2], c[0][nf][3],
                         a[0][0], a[0][1], a[0][2], a[0][3], b0, b1);
                MMA16816(c[1][nf][0], c[1][nf][1], c[1][nf][2], c[1][nf][3],
                         a[1][0], a[1][1], a[1][2], a[1][3], b0, b1);
                MMA16816(c[0][nf+1][0], c[0][nf+1][1], c[0][nf+1][2], c[0][nf+1][3],
                         a[0][0], a[0][1], a[0][2], a[0][3], b2, b3);
                MMA16816(c[1][nf+1][0], c[1][nf+1][1], c[1][nf+1][2], c[1][nf+1][3],
                         a[1][0], a[1][1], a[1][2], a[1][3], b2, b3);
            }
        }

        // ---- bias + relu ----
        #pragma unroll
        for (int nf = 0; nf < 8; nf++) {
            float b0 = bias_s[wn + nf * 8 + 2 * tig];
            float b1 = bias_s[wn + nf * 8 + 2 * tig + 1];
            #pragma unroll
            for (int mf = 0; mf < 2; mf++) {
                c[mf][nf][0] = fmaxf(c[mf][nf][0] + b0, 0.f);
                c[mf][nf][1] = fmaxf(c[mf][nf][1] + b1, 0.f);
                c[mf][nf][2] = fmaxf(c[mf][nf][2] + b0, 0.f);
                c[mf][nf][3] = fmaxf(c[mf][nf][3] + b1, 0.f);
            }
        }

        // ---- per-graph register reduce + direct global atomics ----
        for (int g = g_lo; g <= g_hi; ++g) {
            #pragma unroll
            for (int nf = 0; nf < 8; nf++) {
                float s0 = 0.f, s1 = 0.f;
                #pragma unroll
                for (int mf = 0; mf < 2; mf++) {
                    if (gr0[mf] == g) { s0 += c[mf][nf][0]; s1 += c[mf][nf][1]; }
                    if (gr1[mf] == g) { s0 += c[mf][nf][2]; s1 += c[mf][nf][3]; }
                }
                #pragma unroll
                for (int o = 4; o <= 16; o <<= 1) {
                    s0 += __shfl_xor_sync(0xffffffffu, s0, o);
                    s1 += __shfl_xor_sync(0xffffffffu, s1, o);
                }
                if (lane < 4) {
                    float* dst = &S_out[g * HDIM + wn + nf * 8 + 2 * lane];
                    atomicAdd(dst,     s0);
                    atomicAdd(dst + 1, s1);
                }
            }
        }
    }
}

// ---------------- launch #4: node GEMM (profiled slot) --------------------
__global__ void __launch_bounds__(256, 2)
k_gemm_node(const float* __restrict__ x, const int* __restrict__ batch_idx,
            const float* __restrict__ bn1)
{
    extern __shared__ char smem[];
    uint32_t sbase = (uint32_t)__cvta_generic_to_shared(smem);
    gemm_phase<D_NODE, D_NODE + 8, D_NODE / 16, MTILE * (D_NODE / 4) / 256>(
        x, bn1, d_Wt_node, batch_idx, NODE_TILES, false, d_S_node, smem, sbase);
}

// ---------------- launch #6: edge GEMM -----------------------------------
__global__ void __launch_bounds__(256, 2)
k_gemm_edge(const float* __restrict__ edge_attr, const float* __restrict__ be1)
{
    extern __shared__ char smem[];
    uint32_t sbase = (uint32_t)__cvta_generic_to_shared(smem);
    gemm_phase<D_EDGE, D_EDGE + 8, D_EDGE / 16, MTILE * (D_EDGE / 4) / 256>(
        edge_attr, be1, d_Wt_edge, nullptr, EDGE_TILES, true, d_S_edge, smem, sbase);
}

// ---------------- launch #7: means -> layer-2 -> combine ------------------
__global__ void __launch_bounds__(256)
k_finalize(const float* __restrict__ Wn2, const float* __restrict__ bn2,
           const float* __restrict__ We2, const float* __restrict__ be2,
           const float* __restrict__ Wc,  const float* __restrict__ bc,
           float* __restrict__ out)
{
    __shared__ float mn[8][HDIM], me[8][HDIM], gr[8][HDIM];
    __shared__ int fn[8], fe[8];
    const int tid = threadIdx.x;
    const int gbase = blockIdx.x * 8;

    #pragma unroll
    for (int gg = 0; gg < 8; gg++) {
        int g = gbase + gg;
        int cn = d_cnt_node[g], ce = d_cnt_edge[g];
        if (tid == 0) { fn[gg] = cn; fe[gg] = ce; }
        mn[gg][tid] = (cn > 0) ? d_S_node[g * HDIM + tid] / (float)cn : 0.f;
        me[gg][tid] = (ce > 0) ? d_S_edge[g * HDIM + tid] / (float)ce : 0.f;
    }
    __syncthreads();

    float an[8], ae[8];
    #pragma unroll
    for (int gg = 0; gg < 8; gg++) { an[gg] = 0.f; ae[gg] = 0.f; }
    for (int j = 0; j < HDIM; j++) {
        float w1 = Wn2[j * HDIM + tid];
        float w2 = We2[j * HDIM + tid];
        #pragma unroll
        for (int gg = 0; gg < 8; gg++) {
            an[gg] += mn[gg][j] * w1;
            ae[gg] += me[gg][j] * w2;
        }
    }
    float b2n = bn2[tid], b2e = be2[tid];
    #pragma unroll
    for (int gg = 0; gg < 8; gg++) {
        float nr = (fn[gg] > 0) ? an[gg] + b2n : 0.f;
        float er = (fe[gg] > 0) ? ae[gg] + b2e : 0.f;
        gr[gg][tid] = nr + er;
    }
    __syncthreads();

    float ao[8];
    #pragma unroll
    for (int gg = 0; gg < 8; gg++) ao[gg] = 0.f;
    for (int j = 0; j < HDIM; j++) {
        float w = Wc[j * HDIM + tid];
        #pragma unroll
        for (int gg = 0; gg < 8; gg++) ao[gg] += gr[gg][j] * w;
    }
    float bcv = bc[tid];
    #pragma unroll
    for (int gg = 0; gg < 8; gg++)
        out[(gbase + gg) * HDIM + tid] = ao[gg] + bcv;
}

// ---------------- launch ----------------
extern "C" void kernel_launch(void* const* d_in, const int* in_sizes, int n_in,
                              void* d_out, int out_size)
{
    const float* x         = (const float*)d_in[0];
    const float* edge_attr = (const float*)d_in[1];
    const int*   batch_idx = (const int*)d_in[2];
    const int*   edge_src  = (const int*)d_in[3];
    const float* Wn1 = (const float*)d_in[4];
    const float* bn1 = (const float*)d_in[5];
    const float* Wn2 = (const float*)d_in[6];
    const float* bn2 = (const float*)d_in[7];
    const float* We1 = (const float*)d_in[8];
    const float* be1 = (const float*)d_in[9];
    const float* We2 = (const float*)d_in[10];
    const float* be2 = (const float*)d_in[11];
    const float* Wc  = (const float*)d_in[12];
    const float* bc  = (const float*)d_in[13];
    float* out = (float*)d_out;

    (void)in_sizes; (void)n_in; (void)out_size;

    cudaFuncSetAttribute(k_gemm_node, cudaFuncAttributeMaxDynamicSharedMemorySize, SMEM_BYTES);
    cudaFuncSetAttribute(k_gemm_edge, cudaFuncAttributeMaxDynamicSharedMemorySize, SMEM_BYTES);

    k_zero0<<<1, 512>>>();                                             // #1
    k_setup<<<840, 256>>>(Wn1, We1, batch_idx, edge_src);              // #2
    k_scan<<<1, 512>>>();                                              // #3
    k_gemm_node<<<296, 256, SMEM_BYTES>>>(x, batch_idx, bn1);          // #4 (profiled)
    k_scatter<<<512, 256>>>();                                         // #5
    k_gemm_edge<<<296, 256, SMEM_BYTES>>>(edge_attr, be1);             // #6
    k_finalize<<<64, 256>>>(Wn2, bn2, We2, be2, Wc, bc, out);          // #7
}

// round 8
// speedup vs baseline: 1.5086x; 1.0460x over previous
#include <cuda_runtime.h>
#include <cuda_bf16.h>
#include <cstdint>

// ---------------- problem constants (fixed shapes) ----------------
#define N_NODES 200000
#define N_EDGES 1000000
#define D_NODE  128
#define D_EDGE  64
#define HDIM    256
#define NGRAPH  512

#define MTILE 64
#define NODE_TILES (N_NODES / MTILE)   // 3125 (exact)
#define EDGE_TILES (N_EDGES / MTILE)   // 15625 (exact)
#define NCTA  128                      // output columns per CTA (HDIM split in 2)

// ---------------- scratch (device globals; no allocation) ----------------
__device__ float d_S_node[NGRAPH * HDIM];
__device__ float d_S_edge[NGRAPH * HDIM];
__device__ int   d_cnt_node[NGRAPH];
__device__ int   d_cnt_edge[NGRAPH];
__device__ unsigned short d_eb[N_EDGES];     // graph id per edge
__device__ int   d_esorted[N_EDGES];         // edge ids sorted by graph
__device__ int   d_cursor[NGRAPH];
__device__ __nv_bfloat16 d_Wt_node[HDIM * D_NODE];  // [n][k]  (transposed, bf16)
__device__ __nv_bfloat16 d_Wt_edge[HDIM * D_EDGE];  // [n][k]

// ---------------- asm helpers ----------------
#define LDSM_X4(r0, r1, r2, r3, addr)                                          \
    asm volatile("ldmatrix.sync.aligned.m8n8.x4.shared.b16 {%0,%1,%2,%3}, [%4];" \
                 : "=r"(r0), "=r"(r1), "=r"(r2), "=r"(r3) : "r"(addr))

#define MMA16816(c0, c1, c2, c3, a0, a1, a2, a3, b0, b1)                       \
    asm volatile(                                                              \
        "mma.sync.aligned.m16n8k16.row.col.f32.bf16.bf16.f32 "                 \
        "{%0,%1,%2,%3}, {%4,%5,%6,%7}, {%8,%9}, {%0,%1,%2,%3};\n"              \
        : "+f"(c0), "+f"(c1), "+f"(c2), "+f"(c3)                               \
        : "r"(a0), "r"(a1), "r"(a2), "r"(a3), "r"(b0), "r"(b1))

// ---------------- launch #1: zero count buffers (must precede k_setup) ----
__global__ void k_zero0() {
    int tid = threadIdx.x;
    if (tid < NGRAPH) { d_cnt_node[tid] = 0; d_cnt_edge[tid] = 0; }
}

// ---------------- launch #2: zero sums + weight transpose + histograms ----
__global__ void k_setup(const float* __restrict__ Wn1, const float* __restrict__ We1,
                        const int* __restrict__ batch_idx, const int* __restrict__ edge_src)
{
    const int b = blockIdx.x;
    const int tid = threadIdx.x;
    if (b < 64) {
        int i = b * 256 + tid;
        for (int j = i; j < HDIM * D_NODE; j += 64 * 256) {
            int n = j / D_NODE, k = j % D_NODE;
            d_Wt_node[j] = __float2bfloat16(Wn1[k * HDIM + n]);
        }
        for (int j = i; j < HDIM * D_EDGE; j += 64 * 256) {
            int n = j / D_EDGE, k = j % D_EDGE;
            d_Wt_edge[j] = __float2bfloat16(We1[k * HDIM + n]);
        }
    } else if (b < 128) {
        int i = (b - 64) * 256 + tid;
        for (int j = i; j < NGRAPH * HDIM; j += 64 * 256) { d_S_node[j] = 0.f; d_S_edge[j] = 0.f; }
    } else if (b < 328) {
        __shared__ int h[NGRAPH];
        for (int j = tid; j < NGRAPH; j += 256) h[j] = 0;
        __syncthreads();
        int i = (b - 128) * 256 + tid;
        for (int n = i; n < N_NODES; n += 200 * 256) atomicAdd(&h[batch_idx[n]], 1);
        __syncthreads();
        for (int j = tid; j < NGRAPH; j += 256)
            if (h[j]) atomicAdd(&d_cnt_node[j], h[j]);
    } else {
        __shared__ int h[NGRAPH];
        for (int j = tid; j < NGRAPH; j += 256) h[j] = 0;
        __syncthreads();
        int i = (b - 328) * 256 + tid;
        for (int e = i; e < N_EDGES; e += 512 * 256) {
            int g = batch_idx[edge_src[e]];
            d_eb[e] = (unsigned short)g;
            atomicAdd(&h[g], 1);
        }
        __syncthreads();
        for (int j = tid; j < NGRAPH; j += 256)
            if (h[j]) atomicAdd(&d_cnt_edge[j], h[j]);
    }
}

// ---------------- launch #3: exclusive prefix sum of edge counts ----------
__global__ void k_scan() {
    __shared__ int wsum[16];
    int tid = threadIdx.x;
    int lane = tid & 31, w = tid >> 5;
    int v = d_cnt_edge[tid];
    int s = v;
    #pragma unroll
    for (int o = 1; o < 32; o <<= 1) {
        int t = __shfl_up_sync(0xffffffffu, s, o);
        if (lane >= o) s += t;
    }
    if (lane == 31) wsum[w] = s;
    __syncthreads();
    if (tid == 0) {
        int run = 0;
        for (int i = 0; i < 16; i++) { int t = wsum[i]; wsum[i] = run; run += t; }
    }
    __syncthreads();
    d_cursor[tid] = s + wsum[w] - v;   // exclusive
}

// ---------------- launch #5: counting-sort scatter of edge ids ------------
__global__ void k_scatter() {
    int i = blockIdx.x * blockDim.x + threadIdx.x;
    int stride = gridDim.x * blockDim.x;
    for (int e = i; e < N_EDGES; e += stride) {
        int g = (int)d_eb[e];
        int p = atomicAdd(&d_cursor[g], 1);
        d_esorted[p] = e;
    }
}

// ---------------- first-layer GEMM + segmented column sums ----------------
// N-split: each CTA computes a 64-row x 128-col output tile (nhalf = blockIdx&1).
// 256 threads = 8 warps: wm = (w&1)*32, wn = (w>>1)*32; warp tile 32x32.
// mma m16n8k16 bf16, fp32 accum, LDSM fragment loads.
// Epilogue: per-graph register reduce (shfl over gID) + direct global atomics.
template<int K, int KPAD, int KSTEPS, int NITER>
__device__ __forceinline__ void gemm_phase(
    const float* __restrict__ A_gmem, const float* __restrict__ bias_g,
    const __nv_bfloat16* __restrict__ Wt_g,
    const int* __restrict__ batch_idx, int n_tiles,
    bool is_edge, float* __restrict__ S_out, char* smem, uint32_t sbase)
{
    // smem layout (per CTA): Ws[128][KPAD] bf16 | As[64][KPAD] bf16 | gid[64] | es[64] | bias[128]
    constexpr int WS_BYTES = NCTA * KPAD * 2;
    constexpr int AS_BYTES = MTILE * KPAD * 2;
    __nv_bfloat16* Ws = (__nv_bfloat16*)(smem);
    __nv_bfloat16* As = (__nv_bfloat16*)(smem + WS_BYTES);
    int*   gid_s  = (int*)(smem + WS_BYTES + AS_BYTES);
    int*   es_s   = (int*)(smem + WS_BYTES + AS_BYTES + 256);
    float* bias_s = (float*)(smem + WS_BYTES + AS_BYTES + 512);

    const int tid = threadIdx.x;
    const int nhalf = blockIdx.x & 1;            // fixed per CTA (grid stride is even)
    const int nbase = nhalf * NCTA;

    // load this CTA's half of the transposed weights [n][k] -> padded smem rows
    const uint32_t* Wg32 = (const uint32_t*)Wt_g;
    for (int j = tid; j < NCTA * K / 2; j += 256) {
        int n = j / (K / 2), k2 = j % (K / 2);
        *(uint32_t*)&Ws[n * KPAD + 2 * k2] = Wg32[(nbase + n) * (K / 2) + k2];
    }
    if (tid < NCTA) bias_s[tid] = bias_g[nbase + tid];
    __syncthreads();

    const int lane = tid & 31, warp = tid >> 5;
    const int wm = (warp & 1) * 32;
    const int wn = (warp >> 1) * 32;
    const int gID = lane >> 2, tig = lane & 3;

    // ldmatrix lane addresses (byte offsets in smem window)
    const uint32_t a_addr0 = sbase + WS_BYTES +
        (uint32_t)(((wm + (lane & 15)) * KPAD + ((lane >> 4) << 3)) * 2);
    const uint32_t a_addr1 = a_addr0 + (uint32_t)(16 * KPAD * 2);
    const int brow = (lane & 7) + ((lane >> 4) << 3);
    const int bkof = ((lane >> 3) & 1) << 3;
    const uint32_t b_addr0 = sbase +
        (uint32_t)(((wn + brow) * KPAD + bkof) * 2);

    const int QK = K / 4;   // float4 per row

    for (int b = blockIdx.x; b < 2 * n_tiles; b += gridDim.x) {
        const int t = b >> 1;
        const int r0 = t * MTILE;

        __syncthreads();   // protect gid_s/es_s/As from previous iteration readers
        if (tid < MTILE) {
            int e, gi;
            if (is_edge) { e = d_esorted[r0 + tid]; gi = (int)d_eb[e]; }
            else         { e = r0 + tid;            gi = batch_idx[e]; }
            es_s[tid]  = e;
            gid_s[tid] = gi;
        }
        __syncthreads();

        // ---- gather A tile in chunks of 4 float4 (MLP=4) ----
        #pragma unroll
        for (int base = 0; base < NITER; base += 4) {
            float4 v[4];
            #pragma unroll
            for (int i = 0; i < 4; i++) {
                int j = tid + (base + i) * 256;
                int r = j / QK, q = j % QK;
                v[i] = *(const float4*)(A_gmem + (size_t)es_s[r] * K + q * 4);
            }
            #pragma unroll
            for (int i = 0; i < 4; i++) {
                int j = tid + (base + i) * 256;
                int r = j / QK, q = j % QK;
                __nv_bfloat162 p0 = __float22bfloat162_rn(make_float2(v[i].x, v[i].y));
                __nv_bfloat162 p1 = __float22bfloat162_rn(make_float2(v[i].z, v[i].w));
                *(__nv_bfloat162*)&As[r * KPAD + q * 4]     = p0;
                *(__nv_bfloat162*)&As[r * KPAD + q * 4 + 2] = p1;
            }
        }
        __syncthreads();

        // row gids for this lane's fragment rows
        int gr0[2], gr1[2];
        #pragma unroll
        for (int mf = 0; mf < 2; mf++) {
            gr0[mf] = gid_s[wm + mf * 16 + gID];
            gr1[mf] = gid_s[wm + mf * 16 + gID + 8];
        }
        const int g_lo = gid_s[0];
        const int g_hi = gid_s[MTILE - 1];

        // ---- mainloop (ldmatrix + mma) ----
        float c[2][4][4];
        #pragma unroll
        for (int mf = 0; mf < 2; mf++)
            #pragma unroll
            for (int nf = 0; nf < 4; nf++)
                #pragma unroll
                for (int r = 0; r < 4; r++) c[mf][nf][r] = 0.f;

        #pragma unroll
        for (int ks = 0; ks < KSTEPS; ks++) {
            const uint32_t koff = (uint32_t)(ks * 16 * 2);
            uint32_t a[2][4];
            LDSM_X4(a[0][0], a[0][1], a[0][2], a[0][3], a_addr0 + koff);
            LDSM_X4(a[1][0], a[1][1], a[1][2], a[1][3], a_addr1 + koff);
            #pragma unroll
            for (int nfp = 0; nfp < 2; nfp++) {
                uint32_t b0, b1, b2, b3;
                LDSM_X4(b0, b1, b2, b3,
                        b_addr0 + (uint32_t)(nfp * 16 * KPAD * 2) + koff);
                const int nf = 2 * nfp;
                MMA16816(c[0][nf][0], c[0][nf][1], c[0][nf][2], c[0][nf][3],
                         a[0][0], a[0][1], a[0][2], a[0][3], b0, b1);
                MMA16816(c[1][nf][0], c[1][nf][1], c[1][nf][2], c[1][nf][3],
                         a[1][0], a[1][1], a[1][2], a[1][3], b0, b1);
                MMA16816(c[0][nf+1][0], c[0][nf+1][1], c[0][nf+1][2], c[0][nf+1][3],
                         a[0][0], a[0][1], a[0][2], a[0][3], b2, b3);
                MMA16816(c[1][nf+1][0], c[1][nf+1][1], c[1][nf+1][2], c[1][nf+1][3],
                         a[1][0], a[1][1], a[1][2], a[1][3], b2, b3);
            }
        }

        // ---- bias + relu ----
        #pragma unroll
        for (int nf = 0; nf < 4; nf++) {
            float b0 = bias_s[wn + nf * 8 + 2 * tig];
            float b1 = bias_s[wn + nf * 8 + 2 * tig + 1];
            #pragma unroll
            for (int mf = 0; mf < 2; mf++) {
                c[mf][nf][0] = fmaxf(c[mf][nf][0] + b0, 0.f);
                c[mf][nf][1] = fmaxf(c[mf][nf][1] + b1, 0.f);
                c[mf][nf][2] = fmaxf(c[mf][nf][2] + b0, 0.f);
                c[mf][nf][3] = fmaxf(c[mf][nf][3] + b1, 0.f);
            }
        }

        // ---- per-graph register reduce + direct global atomics ----
        for (int g = g_lo; g <= g_hi; ++g) {
            #pragma unroll
            for (int nf = 0; nf < 4; nf++) {
                float s0 = 0.f, s1 = 0.f;
                #pragma unroll
                for (int mf = 0; mf < 2; mf++) {
                    if (gr0[mf] == g) { s0 += c[mf][nf][0]; s1 += c[mf][nf][1]; }
                    if (gr1[mf] == g) { s0 += c[mf][nf][2]; s1 += c[mf][nf][3]; }
                }
                #pragma unroll
                for (int o = 4; o <= 16; o <<= 1) {
                    s0 += __shfl_xor_sync(0xffffffffu, s0, o);
                    s1 += __shfl_xor_sync(0xffffffffu, s1, o);
                }
                if (lane < 4) {
                    float* dst = &S_out[g * HDIM + nbase + wn + nf * 8 + 2 * lane];
                    atomicAdd(dst,     s0);
                    atomicAdd(dst + 1, s1);
                }
            }
        }
    }
}

#define SMEM_NODE ((NCTA + MTILE) * (D_NODE + 8) * 2 + 1024)   // 53248
#define SMEM_EDGE ((NCTA + MTILE) * (D_EDGE + 8) * 2 + 1024)   // 28672

// ---------------- launch #4: node GEMM (profiled slot) --------------------
__global__ void __launch_bounds__(256, 4)
k_gemm_node(const float* __restrict__ x, const int* __restrict__ batch_idx,
            const float* __restrict__ bn1)
{
    extern __shared__ char smem[];
    uint32_t sbase = (uint32_t)__cvta_generic_to_shared(smem);
    gemm_phase<D_NODE, D_NODE + 8, D_NODE / 16, MTILE * (D_NODE / 4) / 256>(
        x, bn1, d_Wt_node, batch_idx, NODE_TILES, false, d_S_node, smem, sbase);
}

// ---------------- launch #6: edge GEMM -----------------------------------
__global__ void __launch_bounds__(256, 4)
k_gemm_edge(const float* __restrict__ edge_attr, const float* __restrict__ be1)
{
    extern __shared__ char smem[];
    uint32_t sbase = (uint32_t)__cvta_generic_to_shared(smem);
    gemm_phase<D_EDGE, D_EDGE + 8, D_EDGE / 16, MTILE * (D_EDGE / 4) / 256>(
        edge_attr, be1, d_Wt_edge, nullptr, EDGE_TILES, true, d_S_edge, smem, sbase);
}

// ---------------- launch #7: means -> layer-2 -> combine ------------------
__global__ void __launch_bounds__(256)
k_finalize(const float* __restrict__ Wn2, const float* __restrict__ bn2,
           const float* __restrict__ We2, const float* __restrict__ be2,
           const float* __restrict__ Wc,  const float* __restrict__ bc,
           float* __restrict__ out)
{
    __shared__ float mn[8][HDIM], me[8][HDIM], gr[8][HDIM];
    __shared__ int fn[8], fe[8];
    const int tid = threadIdx.x;
    const int gbase = blockIdx.x * 8;

    #pragma unroll
    for (int gg = 0; gg < 8; gg++) {
        int g = gbase + gg;
        int cn = d_cnt_node[g], ce = d_cnt_edge[g];
        if (tid == 0) { fn[gg] = cn; fe[gg] = ce; }
        mn[gg][tid] = (cn > 0) ? d_S_node[g * HDIM + tid] / (float)cn : 0.f;
        me[gg][tid] = (ce > 0) ? d_S_edge[g * HDIM + tid] / (float)ce : 0.f;
    }
    __syncthreads();

    float an[8], ae[8];
    #pragma unroll
    for (int gg = 0; gg < 8; gg++) { an[gg] = 0.f; ae[gg] = 0.f; }
    for (int j = 0; j < HDIM; j++) {
        float w1 = Wn2[j * HDIM + tid];
        float w2 = We2[j * HDIM + tid];
        #pragma unroll
        for (int gg = 0; gg < 8; gg++) {
            an[gg] += mn[gg][j] * w1;
            ae[gg] += me[gg][j] * w2;
        }
    }
    float b2n = bn2[tid], b2e = be2[tid];
    #pragma unroll
    for (int gg = 0; gg < 8; gg++) {
        float nr = (fn[gg] > 0) ? an[gg] + b2n : 0.f;
        float er = (fe[gg] > 0) ? ae[gg] + b2e : 0.f;
        gr[gg][tid] = nr + er;
    }
    __syncthreads();

    float ao[8];
    #pragma unroll
    for (int gg = 0; gg < 8; gg++) ao[gg] = 0.f;
    for (int j = 0; j < HDIM; j++) {
        float w = Wc[j * HDIM + tid];
        #pragma unroll
        for (int gg = 0; gg < 8; gg++) ao[gg] += gr[gg][j] * w;
    }
    float bcv = bc[tid];
    #pragma unroll
    for (int gg = 0; gg < 8; gg++)
        out[(gbase + gg) * HDIM + tid] = ao[gg] + bcv;
}

// ---------------- launch ----------------
extern "C" void kernel_launch(void* const* d_in, const int* in_sizes, int n_in,
                              void* d_out, int out_size)
{
    const float* x         = (const float*)d_in[0];
    const float* edge_attr = (const float*)d_in[1];
    const int*   batch_idx = (const int*)d_in[2];
    const int*   edge_src  = (const int*)d_in[3];
    const float* Wn1 = (const float*)d_in[4];
    const float* bn1 = (const float*)d_in[5];
    const float* Wn2 = (const float*)d_in[6];
    const float* bn2 = (const float*)d_in[7];
    const float* We1 = (const float*)d_in[8];
    const float* be1 = (const float*)d_in[9];
    const float* We2 = (const float*)d_in[10];
    const float* be2 = (const float*)d_in[11];
    const float* Wc  = (const float*)d_in[12];
    const float* bc  = (const float*)d_in[13];
    float* out = (float*)d_out;

    (void)in_sizes; (void)n_in; (void)out_size;

    cudaFuncSetAttribute(k_gemm_node, cudaFuncAttributeMaxDynamicSharedMemorySize, SMEM_NODE);
    cudaFuncSetAttribute(k_gemm_edge, cudaFuncAttributeMaxDynamicSharedMemorySize, SMEM_EDGE);

    k_zero0<<<1, 512>>>();                                             // #1
    k_setup<<<840, 256>>>(Wn1, We1, batch_idx, edge_src);              // #2
    k_scan<<<1, 512>>>();                                              // #3
    k_gemm_node<<<592, 256, SMEM_NODE>>>(x, batch_idx, bn1);           // #4 (profiled)
    k_scatter<<<512, 256>>>();                                         // #5
    k_gemm_edge<<<592, 256, SMEM_EDGE>>>(edge_attr, be1);              // #6
    k_finalize<<<64, 256>>>(Wn2, bn2, We2, be2, Wc, bc, out);          // #7
}